// round 13
// baseline (speedup 1.0000x reference)
#include <cuda_runtime.h>
#include <cuda_fp16.h>
#include <math.h>

#define FD 16
#define HD 16
#define MAXB 131072

// fp16 transposed scratch: g_varh[chunk][row], chunk = f*2+hi (32 chunks),
// each uint4 = 8 half values. 64 MB total (L2-resident).
__device__ uint4 g_varh[(size_t)32 * MAXB];

typedef unsigned long long u64t;

__device__ __forceinline__ float fast_elu(float t) {
    return fmaxf(t, 0.f) + (__expf(fminf(t, 0.f)) - 1.f);
}
__device__ __forceinline__ float fast_sig(float x) {
    float t;
    asm("tanh.approx.f32 %0, %1;" : "=f"(t) : "f"(0.5f * x));
    return fmaf(0.5f, t, 0.5f);
}
// ---- packed f32x2 helpers (Blackwell) ----
__device__ __forceinline__ u64t pk2(float lo, float hi) {
    u64t r;
    asm("mov.b64 %0, {%1, %2};" : "=l"(r) : "r"(__float_as_uint(lo)), "r"(__float_as_uint(hi)));
    return r;
}
__device__ __forceinline__ u64t fma2(u64t a, u64t b, u64t c) {
    u64t d;
    asm("fma.rn.f32x2 %0, %1, %2, %3;" : "=l"(d) : "l"(a), "l"(b), "l"(c));
    return d;
}
__device__ __forceinline__ float hadd2(u64t v) {
    unsigned lo, hi;
    asm("mov.b64 {%0, %1}, %2;" : "=r"(lo), "=r"(hi) : "l"(v));
    return __uint_as_float(lo) + __uint_as_float(hi);
}
__device__ __forceinline__ u64t h2pk(__half2 h) {
    float2 f = __half22float2(h);
    return pk2(f.x, f.y);
}

// ---------------------------------------------------------------------------
// Kernel A (R6-proven, unchanged): per-feature GRN + LayerNorm -> fp16 scratch.
// ---------------------------------------------------------------------------
__global__ __launch_bounds__(128, 4) void var_grn_kernel(
    const float* __restrict__ x_tab,
    const float* __restrict__ emb_w, const float* __restrict__ emb_b,
    const float* __restrict__ w1g, const float* __restrict__ b1g,
    const float* __restrict__ wsg, const float* __restrict__ bsg,
    const float* __restrict__ w2, const float* __restrict__ b2,
    const float* __restrict__ wg, const float* __restrict__ bg,
    const float* __restrict__ gamma, const float* __restrict__ beta,
    int Bn)
{
    __shared__ float sA1[256], sC1[256], sAs[256], sCs[256];
    __shared__ float sW2[4096], sWg[4096];
    __shared__ float sB2[256], sBg[256], sG[256], sBe[256];
    int tid = threadIdx.x;
    for (int t = tid; t < 256; t += 128) {
        int f = t >> 4;
        const float* ew = emb_w + f * 32;
        const float* eb = emb_b + f * 32;
        const float* W1 = w1g + (size_t)t * 32;
        const float* Ws = wsg + (size_t)t * 32;
        float a1 = 0.f, c1 = 0.f, as_ = 0.f, cs = 0.f;
#pragma unroll
        for (int e = 0; e < 32; e++) {
            float we = ew[e], be = eb[e];
            a1  = fmaf(we, W1[e], a1);
            c1  = fmaf(be, W1[e], c1);
            as_ = fmaf(we, Ws[e], as_);
            cs  = fmaf(be, Ws[e], cs);
        }
        sA1[t] = a1;
        sC1[t] = c1 + b1g[t];
        sAs[t] = as_;
        sCs[t] = cs + bsg[t];
        sB2[t] = b2[t];  sBg[t] = bg[t];
        sG[t]  = gamma[t]; sBe[t] = beta[t];
    }
    for (int i = tid; i < 4096; i += 128) { sW2[i] = w2[i]; sWg[i] = wg[i]; }
    __syncthreads();

    int gid = blockIdx.x * 128 + tid;
    int r0 = gid * 2;
    if (r0 >= Bn) return;
    const float* x0 = x_tab + (size_t)r0 * 16;
    const float* x1 = x0 + 16;

#pragma unroll 1
    for (int f = 0; f < 16; f++) {
        int fb = f * 16;
        float xfa = __ldg(x0 + f);
        float xfb = __ldg(x1 + f);

        u64t hap[8], hbp[8];
#pragma unroll
        for (int p = 0; p < 8; p++) {
            float a0 = sA1[fb + 2*p],   c0 = sC1[fb + 2*p];
            float a1 = sA1[fb + 2*p+1], c1 = sC1[fb + 2*p+1];
            hap[p] = pk2(fast_elu(fmaf(xfa, a0, c0)), fast_elu(fmaf(xfa, a1, c1)));
            hbp[p] = pk2(fast_elu(fmaf(xfb, a0, c0)), fast_elu(fmaf(xfb, a1, c1)));
        }
        u64t oap[8], obp[8];
#pragma unroll
        for (int p = 0; p < 8; p++) {
            u64t A0 = 0ull, A1 = 0ull, B0 = 0ull, B1 = 0ull;
            const ulonglong2* w0 = (const ulonglong2*)&sW2[(fb + 2*p) * 16];
            const ulonglong2* w1 = (const ulonglong2*)&sW2[(fb + 2*p+1) * 16];
#pragma unroll
            for (int q = 0; q < 4; q++) {
                ulonglong2 wu0 = w0[q];
                ulonglong2 wu1 = w1[q];
                A0 = fma2(hap[2*q], wu0.x, A0); A0 = fma2(hap[2*q+1], wu0.y, A0);
                B0 = fma2(hbp[2*q], wu0.x, B0); B0 = fma2(hbp[2*q+1], wu0.y, B0);
                A1 = fma2(hap[2*q], wu1.x, A1); A1 = fma2(hap[2*q+1], wu1.y, A1);
                B1 = fma2(hbp[2*q], wu1.x, B1); B1 = fma2(hbp[2*q+1], wu1.y, B1);
            }
            float b0 = sB2[fb + 2*p], b1 = sB2[fb + 2*p+1];
            oap[p] = pk2(b0 + hadd2(A0), b1 + hadd2(A1));
            obp[p] = pk2(b0 + hadd2(B0), b1 + hadd2(B1));
        }
        float va[16], vb[16];
        float mua = 0.f, mub = 0.f;
#pragma unroll
        for (int p = 0; p < 8; p++) {
            u64t A0 = 0ull, A1 = 0ull, B0 = 0ull, B1 = 0ull;
            const ulonglong2* w0 = (const ulonglong2*)&sWg[(fb + 2*p) * 16];
            const ulonglong2* w1 = (const ulonglong2*)&sWg[(fb + 2*p+1) * 16];
#pragma unroll
            for (int q = 0; q < 4; q++) {
                ulonglong2 wu0 = w0[q];
                ulonglong2 wu1 = w1[q];
                A0 = fma2(oap[2*q], wu0.x, A0); A0 = fma2(oap[2*q+1], wu0.y, A0);
                B0 = fma2(obp[2*q], wu0.x, B0); B0 = fma2(obp[2*q+1], wu0.y, B0);
                A1 = fma2(oap[2*q], wu1.x, A1); A1 = fma2(oap[2*q+1], wu1.y, A1);
                B1 = fma2(obp[2*q], wu1.x, B1); B1 = fma2(obp[2*q+1], wu1.y, B1);
            }
            unsigned olo, ohi;
            asm("mov.b64 {%0, %1}, %2;" : "=r"(olo), "=r"(ohi) : "l"(oap[p]));
            float oa0 = __uint_as_float(olo), oa1 = __uint_as_float(ohi);
            asm("mov.b64 {%0, %1}, %2;" : "=r"(olo), "=r"(ohi) : "l"(obp[p]));
            float ob0 = __uint_as_float(olo), ob1 = __uint_as_float(ohi);

            int j0 = fb + 2*p, j1 = fb + 2*p + 1;
            float ga0 = sBg[j0] + hadd2(A0), ga1 = sBg[j1] + hadd2(A1);
            float gb0 = sBg[j0] + hadd2(B0), gb1 = sBg[j1] + hadd2(B1);
            float v00 = fmaf(oa0, fast_sig(ga0), fmaf(xfa, sAs[j0], sCs[j0]));
            float v01 = fmaf(oa1, fast_sig(ga1), fmaf(xfa, sAs[j1], sCs[j1]));
            float v10 = fmaf(ob0, fast_sig(gb0), fmaf(xfb, sAs[j0], sCs[j0]));
            float v11 = fmaf(ob1, fast_sig(gb1), fmaf(xfb, sAs[j1], sCs[j1]));
            va[2*p] = v00; va[2*p+1] = v01;
            vb[2*p] = v10; vb[2*p+1] = v11;
            mua += v00 + v01; mub += v10 + v11;
        }
        mua *= 0.0625f; mub *= 0.0625f;
        float vara = 0.f, varb = 0.f;
#pragma unroll
        for (int j = 0; j < 16; j++) {
            float da = va[j] - mua; vara = fmaf(da, da, vara);
            float db = vb[j] - mub; varb = fmaf(db, db, varb);
        }
        float rsa = rsqrtf(fmaf(vara, 0.0625f, 1e-5f));
        float rsb = rsqrtf(fmaf(varb, 0.0625f, 1e-5f));
#pragma unroll
        for (int hi = 0; hi < 2; hi++) {
            uint4 pa, pb;
            __half2* qa = reinterpret_cast<__half2*>(&pa);
            __half2* qb = reinterpret_cast<__half2*>(&pb);
#pragma unroll
            for (int p = 0; p < 4; p++) {
                int j = hi * 8 + p * 2;
                float g0 = sG[fb+j], g1 = sG[fb+j+1];
                float e0 = sBe[fb+j], e1 = sBe[fb+j+1];
                qa[p] = __floats2half2_rn((va[j]   - mua) * rsa * g0 + e0,
                                          (va[j+1] - mua) * rsa * g1 + e1);
                qb[p] = __floats2half2_rn((vb[j]   - mub) * rsb * g0 + e0,
                                          (vb[j+1] - mub) * rsb * g1 + e1);
            }
            size_t base = (size_t)(f * 2 + hi) * Bn + r0;
            g_varh[base]     = pa;
            g_varh[base + 1] = pb;
        }
    }
}

// ---------------------------------------------------------------------------
// Kernel B (R6 structure, 1 row/thread, u64 accumulators, single pass) with
// MLP/regressor weights via __ldg and smem 36.2 KB -> 5 blocks/SM.
// ---------------------------------------------------------------------------
#define OFF_W1   0
#define OFF_WS   4096
#define OFF_W2   8192
#define OFF_WGG  8448
#define OFF_B1   8704
#define OFF_B2F  8720
#define OFF_BGG  8736
#define OFF_BS   8752
#define OFF_G    8768
#define OFF_BE   8784
#define OFF_MB1  8800
#define OFF_MB2  8864
#define OFF_RB1  8896
#define OFF_RW2  8960
#define OFF_RB2  9024
#define SMEMB_FLOATS 9028

__global__ __launch_bounds__(128, 5) void sel_mlp_kernel(
    const float* __restrict__ wg_w1, const float* __restrict__ wg_b1,
    const float* __restrict__ wg_w2, const float* __restrict__ wg_b2,
    const float* __restrict__ wg_wgm, const float* __restrict__ wg_bg,
    const float* __restrict__ wg_ws, const float* __restrict__ wg_bs,
    const float* __restrict__ wg_g, const float* __restrict__ wg_beta,
    const float* __restrict__ mlp_w1, const float* __restrict__ mlp_b1,
    const float* __restrict__ mlp_w2, const float* __restrict__ mlp_b2,
    const float* __restrict__ reg_w1, const float* __restrict__ reg_b1,
    const float* __restrict__ reg_w2, const float* __restrict__ reg_b2,
    float* __restrict__ out, float* __restrict__ wout, int Bn)
{
    extern __shared__ float s[];
    int tid = threadIdx.x;
    for (int i = tid; i < 4096; i += 128) { s[OFF_W1+i] = wg_w1[i]; s[OFF_WS+i] = wg_ws[i]; }
    for (int i = tid; i < 256; i += 128) { s[OFF_W2+i] = wg_w2[i]; s[OFF_WGG+i] = wg_wgm[i]; }
    if (tid < 64) { s[OFF_MB1+tid] = mlp_b1[tid]; s[OFF_RB1+tid] = reg_b1[tid]; s[OFF_RW2+tid] = reg_w2[tid]; }
    if (tid < 32) s[OFF_MB2+tid] = mlp_b2[tid];
    if (tid < 16) {
        s[OFF_B1+tid]  = wg_b1[tid];  s[OFF_B2F+tid] = wg_b2[tid];
        s[OFF_BGG+tid] = wg_bg[tid];  s[OFF_BS+tid]  = wg_bs[tid];
        s[OFF_G+tid]   = wg_g[tid];   s[OFF_BE+tid]  = wg_beta[tid];
    }
    if (tid == 0) s[OFF_RB2] = reg_b2[0];
    __syncthreads();

    int row = blockIdx.x * 128 + tid;
    if (row >= Bn) return;

    // ---- main contraction: hw/skw (even/odd partial pairs, u64 accums) ----
    u64t hw2[16], sk2[16];
#pragma unroll
    for (int j = 0; j < 16; j++) { hw2[j] = 0ull; sk2[j] = 0ull; }

    const uint4* pvm = g_varh + row;
#pragma unroll 1
    for (int f = 0; f < 16; f++) {
        u64t v2[8];
#pragma unroll
        for (int hi = 0; hi < 2; hi++) {
            uint4 t = pvm[0];
            pvm += Bn;
            const __half2* ph = reinterpret_cast<const __half2*>(&t);
#pragma unroll
            for (int p = 0; p < 4; p++) v2[hi*4 + p] = h2pk(ph[p]);
        }
#pragma unroll
        for (int j = 0; j < 16; j++) {
            const ulonglong2* wa = (const ulonglong2*)&s[OFF_W1 + j * 256 + f * 16];
            const ulonglong2* wb = (const ulonglong2*)&s[OFF_WS + j * 256 + f * 16];
            u64t A = hw2[j], S = sk2[j];
#pragma unroll
            for (int q = 0; q < 4; q++) {
                ulonglong2 w1 = wa[q];
                A = fma2(v2[2*q], w1.x, A); A = fma2(v2[2*q+1], w1.y, A);
                ulonglong2 w2v = wb[q];
                S = fma2(v2[2*q], w2v.x, S); S = fma2(v2[2*q+1], w2v.y, S);
            }
            hw2[j] = A; sk2[j] = S;
        }
    }
    // collapse partials, elu / bias
    u64t hwp[8];
    float skw[16];
#pragma unroll
    for (int p = 0; p < 8; p++) {
        float h0 = fast_elu(hadd2(hw2[2*p])   + s[OFF_B1 + 2*p]);
        float h1 = fast_elu(hadd2(hw2[2*p+1]) + s[OFF_B1 + 2*p+1]);
        hwp[p] = pk2(h0, h1);
        skw[2*p]   = hadd2(sk2[2*p])   + s[OFF_BS + 2*p];
        skw[2*p+1] = hadd2(sk2[2*p+1]) + s[OFF_BS + 2*p+1];
    }
    // ow = hw @ wg_w2.T + b2
    u64t owp[8];
    float ow[16];
#pragma unroll
    for (int p = 0; p < 8; p++) {
        const ulonglong2* w0 = (const ulonglong2*)&s[OFF_W2 + (2*p) * 16];
        const ulonglong2* w1 = (const ulonglong2*)&s[OFF_W2 + (2*p+1) * 16];
        u64t A0 = 0ull, A1 = 0ull;
#pragma unroll
        for (int q = 0; q < 4; q++) {
            ulonglong2 u0 = w0[q], u1 = w1[q];
            A0 = fma2(hwp[2*q], u0.x, A0); A0 = fma2(hwp[2*q+1], u0.y, A0);
            A1 = fma2(hwp[2*q], u1.x, A1); A1 = fma2(hwp[2*q+1], u1.y, A1);
        }
        float o0 = s[OFF_B2F + 2*p]   + hadd2(A0);
        float o1 = s[OFF_B2F + 2*p+1] + hadd2(A1);
        ow[2*p] = o0; ow[2*p+1] = o1;
        owp[p] = pk2(o0, o1);
    }
    // gate + skip + LN
    float l[16];
    float mu = 0.f;
#pragma unroll
    for (int p = 0; p < 8; p++) {
        const ulonglong2* w0 = (const ulonglong2*)&s[OFF_WGG + (2*p) * 16];
        const ulonglong2* w1 = (const ulonglong2*)&s[OFF_WGG + (2*p+1) * 16];
        u64t A0 = 0ull, A1 = 0ull;
#pragma unroll
        for (int q = 0; q < 4; q++) {
            ulonglong2 u0 = w0[q], u1 = w1[q];
            A0 = fma2(owp[2*q], u0.x, A0); A0 = fma2(owp[2*q+1], u0.y, A0);
            A1 = fma2(owp[2*q], u1.x, A1); A1 = fma2(owp[2*q+1], u1.y, A1);
        }
        float g0 = s[OFF_BGG + 2*p]   + hadd2(A0);
        float g1 = s[OFF_BGG + 2*p+1] + hadd2(A1);
        float l0 = fmaf(ow[2*p],   fast_sig(g0), skw[2*p]);
        float l1 = fmaf(ow[2*p+1], fast_sig(g1), skw[2*p+1]);
        l[2*p] = l0; l[2*p+1] = l1;
        mu += l0 + l1;
    }
    mu *= 0.0625f;
    float varv = 0.f;
#pragma unroll
    for (int i = 0; i < 16; i++) { float d = l[i] - mu; varv = fmaf(d, d, varv); }
    float rs = rsqrtf(fmaf(varv, 0.0625f, 1e-5f));
    float wt[16];
    float mx = -1e30f;
#pragma unroll
    for (int i = 0; i < 16; i++) {
        float li = (l[i] - mu) * rs * s[OFF_G + i] + s[OFF_BE + i];
        wt[i] = li;
        mx = fmaxf(mx, li);
    }
    float sum = 0.f;
#pragma unroll
    for (int i = 0; i < 16; i++) { wt[i] = __expf(wt[i] - mx); sum += wt[i]; }
    float inv = 1.f / sum;
#pragma unroll
    for (int i = 0; i < 16; i++) wt[i] *= inv;

    if (wout) {
        float* wo = wout + (size_t)row * 16;
#pragma unroll
        for (int q = 0; q < 4; q++) {
            float4 st; st.x = wt[q*4]; st.y = wt[q*4+1]; st.z = wt[q*4+2]; st.w = wt[q*4+3];
            *(float4*)(wo + q * 4) = st;
        }
    }

    // sel[h] = sum_f v[f,h]*wt[f]  (fp16 re-read, L1/L2-hot, pointer-bumped)
    u64t sel2[8];
#pragma unroll
    for (int p = 0; p < 8; p++) sel2[p] = 0ull;
    const uint4* pv = g_varh + row;
#pragma unroll 1
    for (int f = 0; f < 16; f++) {
        u64t wf2 = pk2(wt[f], wt[f]);
#pragma unroll
        for (int hi = 0; hi < 2; hi++) {
            uint4 t = pv[0];
            pv += Bn;
            const __half2* ph = reinterpret_cast<const __half2*>(&t);
#pragma unroll
            for (int p = 0; p < 4; p++)
                sel2[hi*4+p] = fma2(h2pk(ph[p]), wf2, sel2[hi*4+p]);
        }
    }

    // MLP 16->64->32 (chunked), weights via __ldg (L1-broadcast)
    float m2[32];
#pragma unroll
    for (int i = 0; i < 32; i++) m2[i] = s[OFF_MB2 + i];
#pragma unroll 1
    for (int c = 0; c < 4; c++) {
        u64t m1p[8];
#pragma unroll
        for (int k = 0; k < 8; k++) {
            int i0 = c * 16 + 2*k;
            const ulonglong2* w0 = (const ulonglong2*)(mlp_w1 + i0 * 16);
            const ulonglong2* w1 = (const ulonglong2*)(mlp_w1 + (i0+1) * 16);
            u64t A0 = 0ull, A1 = 0ull;
#pragma unroll
            for (int q = 0; q < 4; q++) {
                ulonglong2 u0 = __ldg(w0 + q), u1 = __ldg(w1 + q);
                A0 = fma2(sel2[2*q], u0.x, A0); A0 = fma2(sel2[2*q+1], u0.y, A0);
                A1 = fma2(sel2[2*q], u1.x, A1); A1 = fma2(sel2[2*q+1], u1.y, A1);
            }
            float v0 = fmaxf(hadd2(A0) + s[OFF_MB1 + i0],     0.f);
            float v1 = fmaxf(hadd2(A1) + s[OFF_MB1 + i0 + 1], 0.f);
            m1p[k] = pk2(v0, v1);
        }
#pragma unroll
        for (int i = 0; i < 32; i++) {
            const ulonglong2* wr = (const ulonglong2*)(mlp_w2 + i * 64 + c * 16);
            u64t A = 0ull;
#pragma unroll
            for (int q = 0; q < 4; q++) {
                ulonglong2 u = __ldg(wr + q);
                A = fma2(m1p[2*q], u.x, A); A = fma2(m1p[2*q+1], u.y, A);
            }
            m2[i] += hadd2(A);
        }
    }
    u64t m2p[16];
#pragma unroll
    for (int p = 0; p < 16; p++)
        m2p[p] = pk2(fmaxf(m2[2*p], 0.f), fmaxf(m2[2*p+1], 0.f));

    // Regressor 32->64->1 (weights via __ldg)
    float acc_out = s[OFF_RB2];
#pragma unroll 4
    for (int i = 0; i < 64; i++) {
        const ulonglong2* wr = (const ulonglong2*)(reg_w1 + i * 32);
        u64t A = 0ull;
#pragma unroll
        for (int q = 0; q < 4; q++) {
            ulonglong2 u = __ldg(wr + q);
            A = fma2(m2p[2*q],   u.x, A);
            A = fma2(m2p[2*q+1], u.y, A);
            u = __ldg(wr + q + 4);
            A = fma2(m2p[8 + 2*q],   u.x, A);
            A = fma2(m2p[8 + 2*q+1], u.y, A);
        }
        float a = fmaxf(hadd2(A) + s[OFF_RB1 + i], 0.f);
        acc_out = fmaf(a, s[OFF_RW2 + i], acc_out);
    }
    out[row] = acc_out;
}

// ---------------------------------------------------------------------------
extern "C" void kernel_launch(void* const* d_in, const int* in_sizes, int n_in,
                              void* d_out, int out_size) {
    const float* x_tab    = (const float*)d_in[0];
    const float* emb_w    = (const float*)d_in[1];
    const float* emb_b    = (const float*)d_in[2];
    const float* grn_w1   = (const float*)d_in[3];
    const float* grn_b1   = (const float*)d_in[4];
    const float* grn_w2   = (const float*)d_in[5];
    const float* grn_b2   = (const float*)d_in[6];
    const float* grn_wg   = (const float*)d_in[7];
    const float* grn_bg   = (const float*)d_in[8];
    const float* grn_ws   = (const float*)d_in[9];
    const float* grn_bs   = (const float*)d_in[10];
    const float* grn_g    = (const float*)d_in[11];
    const float* grn_beta = (const float*)d_in[12];
    const float* wg_w1    = (const float*)d_in[13];
    const float* wg_b1    = (const float*)d_in[14];
    const float* wg_w2    = (const float*)d_in[15];
    const float* wg_b2    = (const float*)d_in[16];
    const float* wg_wgm   = (const float*)d_in[17];
    const float* wg_bg    = (const float*)d_in[18];
    const float* wg_ws    = (const float*)d_in[19];
    const float* wg_bs    = (const float*)d_in[20];
    const float* wg_g     = (const float*)d_in[21];
    const float* wg_beta  = (const float*)d_in[22];
    const float* mlp_w1   = (const float*)d_in[23];
    const float* mlp_b1   = (const float*)d_in[24];
    const float* mlp_w2   = (const float*)d_in[25];
    const float* mlp_b2   = (const float*)d_in[26];
    const float* reg_w1   = (const float*)d_in[27];
    const float* reg_b1   = (const float*)d_in[28];
    const float* reg_w2   = (const float*)d_in[29];
    const float* reg_b2   = (const float*)d_in[30];

    int Bn = in_sizes[0] / FD;
    float* out = (float*)d_out;
    float* wout = (out_size >= Bn * (FD + 1)) ? (out + Bn) : nullptr;

    cudaFuncSetAttribute(sel_mlp_kernel,
                         cudaFuncAttributeMaxDynamicSharedMemorySize,
                         SMEMB_FLOATS * (int)sizeof(float));

    int gridA = (Bn + 255) / 256;   // 128 threads x 2 rows
    var_grn_kernel<<<gridA, 128>>>(x_tab, emb_w, emb_b, grn_w1, grn_b1,
                                   grn_ws, grn_bs, grn_w2, grn_b2, grn_wg,
                                   grn_bg, grn_g, grn_beta, Bn);

    int gridB = (Bn + 127) / 128;   // 128 threads x 1 row
    sel_mlp_kernel<<<gridB, 128, SMEMB_FLOATS * sizeof(float)>>>(
        wg_w1, wg_b1, wg_w2, wg_b2, wg_wgm, wg_bg, wg_ws, wg_bs, wg_g, wg_beta,
        mlp_w1, mlp_b1, mlp_w2, mlp_b2, reg_w1, reg_b1, reg_w2, reg_b2,
        out, wout, Bn);
}

// round 14
// speedup vs baseline: 1.6299x; 1.6299x over previous
#include <cuda_runtime.h>
#include <cuda_fp16.h>
#include <math.h>

#define FD 16
#define HD 16
#define MAXB 131072

// fp16 transposed scratch: g_varh[chunk][row], chunk = f*2+hi (32 chunks),
// each uint4 = 8 half values. 64 MB total (L2-resident).
__device__ uint4 g_varh[(size_t)32 * MAXB];

typedef unsigned long long u64t;

__device__ __forceinline__ float fast_elu(float t) {
    return fmaxf(t, 0.f) + (__expf(fminf(t, 0.f)) - 1.f);
}
__device__ __forceinline__ float fast_sig(float x) {
    float t;
    asm("tanh.approx.f32 %0, %1;" : "=f"(t) : "f"(0.5f * x));
    return fmaf(0.5f, t, 0.5f);
}
// ---- packed f32x2 helpers (Blackwell) ----
__device__ __forceinline__ u64t pk2(float lo, float hi) {
    u64t r;
    asm("mov.b64 %0, {%1, %2};" : "=l"(r) : "r"(__float_as_uint(lo)), "r"(__float_as_uint(hi)));
    return r;
}
__device__ __forceinline__ u64t fma2(u64t a, u64t b, u64t c) {
    u64t d;
    asm("fma.rn.f32x2 %0, %1, %2, %3;" : "=l"(d) : "l"(a), "l"(b), "l"(c));
    return d;
}
__device__ __forceinline__ u64t add2(u64t a, u64t b) {
    u64t d;
    asm("add.rn.f32x2 %0, %1, %2;" : "=l"(d) : "l"(a), "l"(b));
    return d;
}
__device__ __forceinline__ float hadd2(u64t v) {
    unsigned lo, hi;
    asm("mov.b64 {%0, %1}, %2;" : "=r"(lo), "=r"(hi) : "l"(v));
    return __uint_as_float(lo) + __uint_as_float(hi);
}
__device__ __forceinline__ u64t h2pk(__half2 h) {
    float2 f = __half22float2(h);
    return pk2(f.x, f.y);
}

// ---------------------------------------------------------------------------
// Kernel A (R6-proven, unchanged): per-feature GRN + LayerNorm -> fp16 scratch.
// ---------------------------------------------------------------------------
__global__ __launch_bounds__(128, 4) void var_grn_kernel(
    const float* __restrict__ x_tab,
    const float* __restrict__ emb_w, const float* __restrict__ emb_b,
    const float* __restrict__ w1g, const float* __restrict__ b1g,
    const float* __restrict__ wsg, const float* __restrict__ bsg,
    const float* __restrict__ w2, const float* __restrict__ b2,
    const float* __restrict__ wg, const float* __restrict__ bg,
    const float* __restrict__ gamma, const float* __restrict__ beta,
    int Bn)
{
    __shared__ float sA1[256], sC1[256], sAs[256], sCs[256];
    __shared__ float sW2[4096], sWg[4096];
    __shared__ float sB2[256], sBg[256], sG[256], sBe[256];
    int tid = threadIdx.x;
    for (int t = tid; t < 256; t += 128) {
        int f = t >> 4;
        const float* ew = emb_w + f * 32;
        const float* eb = emb_b + f * 32;
        const float* W1 = w1g + (size_t)t * 32;
        const float* Ws = wsg + (size_t)t * 32;
        float a1 = 0.f, c1 = 0.f, as_ = 0.f, cs = 0.f;
#pragma unroll
        for (int e = 0; e < 32; e++) {
            float we = ew[e], be = eb[e];
            a1  = fmaf(we, W1[e], a1);
            c1  = fmaf(be, W1[e], c1);
            as_ = fmaf(we, Ws[e], as_);
            cs  = fmaf(be, Ws[e], cs);
        }
        sA1[t] = a1;
        sC1[t] = c1 + b1g[t];
        sAs[t] = as_;
        sCs[t] = cs + bsg[t];
        sB2[t] = b2[t];  sBg[t] = bg[t];
        sG[t]  = gamma[t]; sBe[t] = beta[t];
    }
    for (int i = tid; i < 4096; i += 128) { sW2[i] = w2[i]; sWg[i] = wg[i]; }
    __syncthreads();

    int gid = blockIdx.x * 128 + tid;
    int r0 = gid * 2;
    if (r0 >= Bn) return;
    const float* x0 = x_tab + (size_t)r0 * 16;
    const float* x1 = x0 + 16;

#pragma unroll 1
    for (int f = 0; f < 16; f++) {
        int fb = f * 16;
        float xfa = __ldg(x0 + f);
        float xfb = __ldg(x1 + f);

        u64t hap[8], hbp[8];
#pragma unroll
        for (int p = 0; p < 8; p++) {
            float a0 = sA1[fb + 2*p],   c0 = sC1[fb + 2*p];
            float a1 = sA1[fb + 2*p+1], c1 = sC1[fb + 2*p+1];
            hap[p] = pk2(fast_elu(fmaf(xfa, a0, c0)), fast_elu(fmaf(xfa, a1, c1)));
            hbp[p] = pk2(fast_elu(fmaf(xfb, a0, c0)), fast_elu(fmaf(xfb, a1, c1)));
        }
        u64t oap[8], obp[8];
#pragma unroll
        for (int p = 0; p < 8; p++) {
            u64t A0 = 0ull, A1 = 0ull, B0 = 0ull, B1 = 0ull;
            const ulonglong2* w0 = (const ulonglong2*)&sW2[(fb + 2*p) * 16];
            const ulonglong2* w1 = (const ulonglong2*)&sW2[(fb + 2*p+1) * 16];
#pragma unroll
            for (int q = 0; q < 4; q++) {
                ulonglong2 wu0 = w0[q];
                ulonglong2 wu1 = w1[q];
                A0 = fma2(hap[2*q], wu0.x, A0); A0 = fma2(hap[2*q+1], wu0.y, A0);
                B0 = fma2(hbp[2*q], wu0.x, B0); B0 = fma2(hbp[2*q+1], wu0.y, B0);
                A1 = fma2(hap[2*q], wu1.x, A1); A1 = fma2(hap[2*q+1], wu1.y, A1);
                B1 = fma2(hbp[2*q], wu1.x, B1); B1 = fma2(hbp[2*q+1], wu1.y, B1);
            }
            float b0 = sB2[fb + 2*p], b1 = sB2[fb + 2*p+1];
            oap[p] = pk2(b0 + hadd2(A0), b1 + hadd2(A1));
            obp[p] = pk2(b0 + hadd2(B0), b1 + hadd2(B1));
        }
        float va[16], vb[16];
        float mua = 0.f, mub = 0.f;
#pragma unroll
        for (int p = 0; p < 8; p++) {
            u64t A0 = 0ull, A1 = 0ull, B0 = 0ull, B1 = 0ull;
            const ulonglong2* w0 = (const ulonglong2*)&sWg[(fb + 2*p) * 16];
            const ulonglong2* w1 = (const ulonglong2*)&sWg[(fb + 2*p+1) * 16];
#pragma unroll
            for (int q = 0; q < 4; q++) {
                ulonglong2 wu0 = w0[q];
                ulonglong2 wu1 = w1[q];
                A0 = fma2(oap[2*q], wu0.x, A0); A0 = fma2(oap[2*q+1], wu0.y, A0);
                B0 = fma2(obp[2*q], wu0.x, B0); B0 = fma2(obp[2*q+1], wu0.y, B0);
                A1 = fma2(oap[2*q], wu1.x, A1); A1 = fma2(oap[2*q+1], wu1.y, A1);
                B1 = fma2(obp[2*q], wu1.x, B1); B1 = fma2(obp[2*q+1], wu1.y, B1);
            }
            unsigned olo, ohi;
            asm("mov.b64 {%0, %1}, %2;" : "=r"(olo), "=r"(ohi) : "l"(oap[p]));
            float oa0 = __uint_as_float(olo), oa1 = __uint_as_float(ohi);
            asm("mov.b64 {%0, %1}, %2;" : "=r"(olo), "=r"(ohi) : "l"(obp[p]));
            float ob0 = __uint_as_float(olo), ob1 = __uint_as_float(ohi);

            int j0 = fb + 2*p, j1 = fb + 2*p + 1;
            float ga0 = sBg[j0] + hadd2(A0), ga1 = sBg[j1] + hadd2(A1);
            float gb0 = sBg[j0] + hadd2(B0), gb1 = sBg[j1] + hadd2(B1);
            float v00 = fmaf(oa0, fast_sig(ga0), fmaf(xfa, sAs[j0], sCs[j0]));
            float v01 = fmaf(oa1, fast_sig(ga1), fmaf(xfa, sAs[j1], sCs[j1]));
            float v10 = fmaf(ob0, fast_sig(gb0), fmaf(xfb, sAs[j0], sCs[j0]));
            float v11 = fmaf(ob1, fast_sig(gb1), fmaf(xfb, sAs[j1], sCs[j1]));
            va[2*p] = v00; va[2*p+1] = v01;
            vb[2*p] = v10; vb[2*p+1] = v11;
            mua += v00 + v01; mub += v10 + v11;
        }
        mua *= 0.0625f; mub *= 0.0625f;
        float vara = 0.f, varb = 0.f;
#pragma unroll
        for (int j = 0; j < 16; j++) {
            float da = va[j] - mua; vara = fmaf(da, da, vara);
            float db = vb[j] - mub; varb = fmaf(db, db, varb);
        }
        float rsa = rsqrtf(fmaf(vara, 0.0625f, 1e-5f));
        float rsb = rsqrtf(fmaf(varb, 0.0625f, 1e-5f));
#pragma unroll
        for (int hi = 0; hi < 2; hi++) {
            uint4 pa, pb;
            __half2* qa = reinterpret_cast<__half2*>(&pa);
            __half2* qb = reinterpret_cast<__half2*>(&pb);
#pragma unroll
            for (int p = 0; p < 4; p++) {
                int j = hi * 8 + p * 2;
                float g0 = sG[fb+j], g1 = sG[fb+j+1];
                float e0 = sBe[fb+j], e1 = sBe[fb+j+1];
                qa[p] = __floats2half2_rn((va[j]   - mua) * rsa * g0 + e0,
                                          (va[j+1] - mua) * rsa * g1 + e1);
                qb[p] = __floats2half2_rn((vb[j]   - mub) * rsb * g0 + e0,
                                          (vb[j+1] - mub) * rsb * g1 + e1);
            }
            size_t base = (size_t)(f * 2 + hi) * Bn + r0;
            g_varh[base]     = pa;
            g_varh[base + 1] = pb;
        }
    }
}

// ---------------------------------------------------------------------------
// Kernel B: R6 layout/structure exactly (1 row/thread, 56.6 KB smem, 128 regs)
// with ONE change: main-loop accumulation via 4 transient depth-4 chains
// folded with add.rn.f32x2 (breaks the 8-deep fma2 dependency chains).
// ---------------------------------------------------------------------------
#define OFF_W1   0
#define OFF_WS   4096
#define OFF_W2   8192
#define OFF_WGG  8448
#define OFF_MW1  8704
#define OFF_MW2  9728
#define OFF_RW1  11776
#define OFF_B1   13824
#define OFF_B2F  13840
#define OFF_BGG  13856
#define OFF_BS   13872
#define OFF_G    13888
#define OFF_BE   13904
#define OFF_MB1  13920
#define OFF_MB2  13984
#define OFF_RB1  14016
#define OFF_RW2  14080
#define OFF_RB2  14144
#define SMEMB_FLOATS 14148

__global__ __launch_bounds__(128, 4) void sel_mlp_kernel(
    const float* __restrict__ wg_w1, const float* __restrict__ wg_b1,
    const float* __restrict__ wg_w2, const float* __restrict__ wg_b2,
    const float* __restrict__ wg_wgm, const float* __restrict__ wg_bg,
    const float* __restrict__ wg_ws, const float* __restrict__ wg_bs,
    const float* __restrict__ wg_g, const float* __restrict__ wg_beta,
    const float* __restrict__ mlp_w1, const float* __restrict__ mlp_b1,
    const float* __restrict__ mlp_w2, const float* __restrict__ mlp_b2,
    const float* __restrict__ reg_w1, const float* __restrict__ reg_b1,
    const float* __restrict__ reg_w2, const float* __restrict__ reg_b2,
    float* __restrict__ out, float* __restrict__ wout, int Bn)
{
    extern __shared__ float s[];
    int tid = threadIdx.x;
    for (int i = tid; i < 4096; i += 128) { s[OFF_W1+i] = wg_w1[i]; s[OFF_WS+i] = wg_ws[i]; }
    for (int i = tid; i < 2048; i += 128) { s[OFF_MW2+i] = mlp_w2[i]; s[OFF_RW1+i] = reg_w1[i]; }
    for (int i = tid; i < 1024; i += 128) s[OFF_MW1+i] = mlp_w1[i];
    for (int i = tid; i < 256; i += 128) { s[OFF_W2+i] = wg_w2[i]; s[OFF_WGG+i] = wg_wgm[i]; }
    if (tid < 64) { s[OFF_MB1+tid] = mlp_b1[tid]; s[OFF_RB1+tid] = reg_b1[tid]; s[OFF_RW2+tid] = reg_w2[tid]; }
    if (tid < 32) s[OFF_MB2+tid] = mlp_b2[tid];
    if (tid < 16) {
        s[OFF_B1+tid]  = wg_b1[tid];  s[OFF_B2F+tid] = wg_b2[tid];
        s[OFF_BGG+tid] = wg_bg[tid];  s[OFF_BS+tid]  = wg_bs[tid];
        s[OFF_G+tid]   = wg_g[tid];   s[OFF_BE+tid]  = wg_beta[tid];
    }
    if (tid == 0) s[OFF_RB2] = reg_b2[0];
    __syncthreads();

    int row = blockIdx.x * 128 + tid;
    if (row >= Bn) return;

    // ---- main contraction: hw/skw with transient split chains ----
    u64t hw2[16], sk2[16];
#pragma unroll
    for (int j = 0; j < 16; j++) { hw2[j] = 0ull; sk2[j] = 0ull; }

    const uint4* pvm = g_varh + row;
#pragma unroll 1
    for (int f = 0; f < 16; f++) {
        u64t v2[8];
#pragma unroll
        for (int hi = 0; hi < 2; hi++) {
            uint4 t = pvm[0];
            pvm += Bn;
            const __half2* ph = reinterpret_cast<const __half2*>(&t);
#pragma unroll
            for (int p = 0; p < 4; p++) v2[hi*4 + p] = h2pk(ph[p]);
        }
#pragma unroll
        for (int j = 0; j < 16; j++) {
            const ulonglong2* wa = (const ulonglong2*)&s[OFF_W1 + j * 256 + f * 16];
            const ulonglong2* wb = (const ulonglong2*)&s[OFF_WS + j * 256 + f * 16];
            u64t A0 = 0ull, A1 = 0ull, S0 = 0ull, S1 = 0ull;
#pragma unroll
            for (int q = 0; q < 4; q++) {
                ulonglong2 w1 = wa[q];
                A0 = fma2(v2[2*q],   w1.x, A0);
                A1 = fma2(v2[2*q+1], w1.y, A1);
                ulonglong2 w2v = wb[q];
                S0 = fma2(v2[2*q],   w2v.x, S0);
                S1 = fma2(v2[2*q+1], w2v.y, S1);
            }
            hw2[j] = add2(hw2[j], add2(A0, A1));
            sk2[j] = add2(sk2[j], add2(S0, S1));
        }
    }
    // collapse partials, elu / bias
    u64t hwp[8];
    float skw[16];
#pragma unroll
    for (int p = 0; p < 8; p++) {
        float h0 = fast_elu(hadd2(hw2[2*p])   + s[OFF_B1 + 2*p]);
        float h1 = fast_elu(hadd2(hw2[2*p+1]) + s[OFF_B1 + 2*p+1]);
        hwp[p] = pk2(h0, h1);
        skw[2*p]   = hadd2(sk2[2*p])   + s[OFF_BS + 2*p];
        skw[2*p+1] = hadd2(sk2[2*p+1]) + s[OFF_BS + 2*p+1];
    }
    // ow = hw @ wg_w2.T + b2
    u64t owp[8];
    float ow[16];
#pragma unroll
    for (int p = 0; p < 8; p++) {
        const ulonglong2* w0 = (const ulonglong2*)&s[OFF_W2 + (2*p) * 16];
        const ulonglong2* w1 = (const ulonglong2*)&s[OFF_W2 + (2*p+1) * 16];
        u64t A0 = 0ull, A1 = 0ull;
#pragma unroll
        for (int q = 0; q < 4; q++) {
            ulonglong2 u0 = w0[q], u1 = w1[q];
            A0 = fma2(hwp[2*q], u0.x, A0); A0 = fma2(hwp[2*q+1], u0.y, A0);
            A1 = fma2(hwp[2*q], u1.x, A1); A1 = fma2(hwp[2*q+1], u1.y, A1);
        }
        float o0 = s[OFF_B2F + 2*p]   + hadd2(A0);
        float o1 = s[OFF_B2F + 2*p+1] + hadd2(A1);
        ow[2*p] = o0; ow[2*p+1] = o1;
        owp[p] = pk2(o0, o1);
    }
    // gate + skip + LN
    float l[16];
    float mu = 0.f;
#pragma unroll
    for (int p = 0; p < 8; p++) {
        const ulonglong2* w0 = (const ulonglong2*)&s[OFF_WGG + (2*p) * 16];
        const ulonglong2* w1 = (const ulonglong2*)&s[OFF_WGG + (2*p+1) * 16];
        u64t A0 = 0ull, A1 = 0ull;
#pragma unroll
        for (int q = 0; q < 4; q++) {
            ulonglong2 u0 = w0[q], u1 = w1[q];
            A0 = fma2(owp[2*q], u0.x, A0); A0 = fma2(owp[2*q+1], u0.y, A0);
            A1 = fma2(owp[2*q], u1.x, A1); A1 = fma2(owp[2*q+1], u1.y, A1);
        }
        float g0 = s[OFF_BGG + 2*p]   + hadd2(A0);
        float g1 = s[OFF_BGG + 2*p+1] + hadd2(A1);
        float l0 = fmaf(ow[2*p],   fast_sig(g0), skw[2*p]);
        float l1 = fmaf(ow[2*p+1], fast_sig(g1), skw[2*p+1]);
        l[2*p] = l0; l[2*p+1] = l1;
        mu += l0 + l1;
    }
    mu *= 0.0625f;
    float varv = 0.f;
#pragma unroll
    for (int i = 0; i < 16; i++) { float d = l[i] - mu; varv = fmaf(d, d, varv); }
    float rs = rsqrtf(fmaf(varv, 0.0625f, 1e-5f));
    float wt[16];
    float mx = -1e30f;
#pragma unroll
    for (int i = 0; i < 16; i++) {
        float li = (l[i] - mu) * rs * s[OFF_G + i] + s[OFF_BE + i];
        wt[i] = li;
        mx = fmaxf(mx, li);
    }
    float sum = 0.f;
#pragma unroll
    for (int i = 0; i < 16; i++) { wt[i] = __expf(wt[i] - mx); sum += wt[i]; }
    float inv = 1.f / sum;
#pragma unroll
    for (int i = 0; i < 16; i++) wt[i] *= inv;

    if (wout) {
        float* wo = wout + (size_t)row * 16;
#pragma unroll
        for (int q = 0; q < 4; q++) {
            float4 st; st.x = wt[q*4]; st.y = wt[q*4+1]; st.z = wt[q*4+2]; st.w = wt[q*4+3];
            *(float4*)(wo + q * 4) = st;
        }
    }

    // sel[h] = sum_f v[f,h]*wt[f]  (fp16 re-read, L1/L2-hot, pointer-bumped)
    u64t sel2[8];
#pragma unroll
    for (int p = 0; p < 8; p++) sel2[p] = 0ull;
    const uint4* pv = g_varh + row;
#pragma unroll 1
    for (int f = 0; f < 16; f++) {
        u64t wf2 = pk2(wt[f], wt[f]);
#pragma unroll
        for (int hi = 0; hi < 2; hi++) {
            uint4 t = pv[0];
            pv += Bn;
            const __half2* ph = reinterpret_cast<const __half2*>(&t);
#pragma unroll
            for (int p = 0; p < 4; p++)
                sel2[hi*4+p] = fma2(h2pk(ph[p]), wf2, sel2[hi*4+p]);
        }
    }

    // MLP 16->64->32 (chunked) with packed pairs
    float m2[32];
#pragma unroll
    for (int i = 0; i < 32; i++) m2[i] = s[OFF_MB2 + i];
#pragma unroll 1
    for (int c = 0; c < 4; c++) {
        u64t m1p[8];
#pragma unroll
        for (int k = 0; k < 8; k++) {
            int i0 = c * 16 + 2*k;
            const ulonglong2* w0 = (const ulonglong2*)&s[OFF_MW1 + i0 * 16];
            const ulonglong2* w1 = (const ulonglong2*)&s[OFF_MW1 + (i0+1) * 16];
            u64t A0 = 0ull, A1 = 0ull;
#pragma unroll
            for (int q = 0; q < 4; q++) {
                ulonglong2 u0 = w0[q], u1 = w1[q];
                A0 = fma2(sel2[2*q], u0.x, A0); A0 = fma2(sel2[2*q+1], u0.y, A0);
                A1 = fma2(sel2[2*q], u1.x, A1); A1 = fma2(sel2[2*q+1], u1.y, A1);
            }
            float v0 = fmaxf(hadd2(A0) + s[OFF_MB1 + i0],     0.f);
            float v1 = fmaxf(hadd2(A1) + s[OFF_MB1 + i0 + 1], 0.f);
            m1p[k] = pk2(v0, v1);
        }
#pragma unroll
        for (int i = 0; i < 32; i++) {
            const ulonglong2* wr = (const ulonglong2*)&s[OFF_MW2 + i * 64 + c * 16];
            u64t A = 0ull;
#pragma unroll
            for (int q = 0; q < 4; q++) {
                ulonglong2 u = wr[q];
                A = fma2(m1p[2*q], u.x, A); A = fma2(m1p[2*q+1], u.y, A);
            }
            m2[i] += hadd2(A);
        }
    }
    u64t m2p[16];
#pragma unroll
    for (int p = 0; p < 16; p++)
        m2p[p] = pk2(fmaxf(m2[2*p], 0.f), fmaxf(m2[2*p+1], 0.f));

    // Regressor 32->64->1
    float acc_out = s[OFF_RB2];
#pragma unroll 4
    for (int i = 0; i < 64; i++) {
        const ulonglong2* wr = (const ulonglong2*)&s[OFF_RW1 + i * 32];
        u64t A = 0ull;
#pragma unroll
        for (int q = 0; q < 4; q++) {
            ulonglong2 u = wr[q];
            A = fma2(m2p[2*q],   u.x, A);
            A = fma2(m2p[2*q+1], u.y, A);
            u = wr[q + 4];
            A = fma2(m2p[8 + 2*q],   u.x, A);
            A = fma2(m2p[8 + 2*q+1], u.y, A);
        }
        float a = fmaxf(hadd2(A) + s[OFF_RB1 + i], 0.f);
        acc_out = fmaf(a, s[OFF_RW2 + i], acc_out);
    }
    out[row] = acc_out;
}

// ---------------------------------------------------------------------------
extern "C" void kernel_launch(void* const* d_in, const int* in_sizes, int n_in,
                              void* d_out, int out_size) {
    const float* x_tab    = (const float*)d_in[0];
    const float* emb_w    = (const float*)d_in[1];
    const float* emb_b    = (const float*)d_in[2];
    const float* grn_w1   = (const float*)d_in[3];
    const float* grn_b1   = (const float*)d_in[4];
    const float* grn_w2   = (const float*)d_in[5];
    const float* grn_b2   = (const float*)d_in[6];
    const float* grn_wg   = (const float*)d_in[7];
    const float* grn_bg   = (const float*)d_in[8];
    const float* grn_ws   = (const float*)d_in[9];
    const float* grn_bs   = (const float*)d_in[10];
    const float* grn_g    = (const float*)d_in[11];
    const float* grn_beta = (const float*)d_in[12];
    const float* wg_w1    = (const float*)d_in[13];
    const float* wg_b1    = (const float*)d_in[14];
    const float* wg_w2    = (const float*)d_in[15];
    const float* wg_b2    = (const float*)d_in[16];
    const float* wg_wgm   = (const float*)d_in[17];
    const float* wg_bg    = (const float*)d_in[18];
    const float* wg_ws    = (const float*)d_in[19];
    const float* wg_bs    = (const float*)d_in[20];
    const float* wg_g     = (const float*)d_in[21];
    const float* wg_beta  = (const float*)d_in[22];
    const float* mlp_w1   = (const float*)d_in[23];
    const float* mlp_b1   = (const float*)d_in[24];
    const float* mlp_w2   = (const float*)d_in[25];
    const float* mlp_b2   = (const float*)d_in[26];
    const float* reg_w1   = (const float*)d_in[27];
    const float* reg_b1   = (const float*)d_in[28];
    const float* reg_w2   = (const float*)d_in[29];
    const float* reg_b2   = (const float*)d_in[30];

    int Bn = in_sizes[0] / FD;
    float* out = (float*)d_out;
    float* wout = (out_size >= Bn * (FD + 1)) ? (out + Bn) : nullptr;

    cudaFuncSetAttribute(sel_mlp_kernel,
                         cudaFuncAttributeMaxDynamicSharedMemorySize,
                         SMEMB_FLOATS * (int)sizeof(float));

    int gridA = (Bn + 255) / 256;   // 128 threads x 2 rows
    var_grn_kernel<<<gridA, 128>>>(x_tab, emb_w, emb_b, grn_w1, grn_b1,
                                   grn_ws, grn_bs, grn_w2, grn_b2, grn_wg,
                                   grn_bg, grn_g, grn_beta, Bn);

    int gridB = (Bn + 127) / 128;   // 128 threads x 1 row
    sel_mlp_kernel<<<gridB, 128, SMEMB_FLOATS * sizeof(float)>>>(
        wg_w1, wg_b1, wg_w2, wg_b2, wg_wgm, wg_bg, wg_ws, wg_bs, wg_g, wg_beta,
        mlp_w1, mlp_b1, mlp_w2, mlp_b2, reg_w1, reg_b1, reg_w2, reg_b2,
        out, wout, Bn);
}